// round 12
// baseline (speedup 1.0000x reference)
#include <cuda_runtime.h>
#include <mma.h>
#include <math.h>
#include <stdint.h>

using namespace nvcuda;

// Problem constants
#define BATCH   4
#define SEQ     2048
#define DDIM    1024
#define NHEADS  16
#define HDIM    64
#define MROWS   (BATCH*SEQ)   // 8192
#define SCALE   0.125f        // 1/sqrt(64)

// Scratch (allocation-free rule: __device__ globals)
__device__ float g_Q[MROWS*DDIM];
__device__ float g_K[MROWS*DDIM];
__device__ float g_V[MROWS*DDIM];
__device__ float g_ctx[MROWS*DDIM];

// ---------------------------------------------------------------------------
// cp.async helpers (16B, L1-bypass) — used ONLY in the GEMM this round
// (bisect: flash kernel is the byte-identical R6 version, no cp.async).
// ---------------------------------------------------------------------------
__device__ __forceinline__ void cp16(unsigned int dst_smem, const void* src) {
    asm volatile("cp.async.cg.shared.global [%0], [%1], 16;\n"
                 :: "r"(dst_smem), "l"(src));
}
#define CP_COMMIT() asm volatile("cp.async.commit_group;\n" ::: "memory")
#define CP_WAIT0()  asm volatile("cp.async.wait_group 0;\n" ::: "memory")

__device__ __forceinline__ unsigned int smem_u32(const void* p) {
    return (unsigned int)__cvta_generic_to_shared(p);
}

// round all fragment elements to tf32 (RN) in registers
template <class Frag>
__device__ __forceinline__ void frag_to_tf32(Frag& f) {
    #pragma unroll
    for (int i = 0; i < f.num_elements; i++)
        f.x[i] = wmma::__float_to_tf32(f.x[i]);
}

// ---------------------------------------------------------------------------
// TF32 GEMM with bias, cp.async double-buffered: C = A @ W + b
// BM=128, BN=128, BK=16, 256 threads (8 warps), warp tile 32x64.
// Raw fp32 tiles land in smem via LDGSTS; tf32 rounding happens on fragment
// registers (24 cvt/warp/k-step). CVT_OUT: epilogue writes tf32-rounded
// values so downstream consumers' conversions are idempotent.
// ---------------------------------------------------------------------------
template <bool CVT_OUT>
__global__ void __launch_bounds__(256) gemm_tf32_bias(
    const float* __restrict__ A, const float* __restrict__ W,
    const float* __restrict__ bias, float* __restrict__ C,
    int M, int N, int K)
{
    __shared__ float As[2][128][24];    // [buf][m][k]
    __shared__ float Bs[2][16][136];    // [buf][k][n]

    const int tid  = threadIdx.x;
    const int warp = tid >> 5;
    const int lane = tid & 31;
    const int wr   = warp >> 1;   // 0..3  -> rows wr*32
    const int wc   = warp & 1;    // 0..1  -> cols wc*64
    const int bm   = blockIdx.y * 128;
    const int bn   = blockIdx.x * 128;

    wmma::fragment<wmma::accumulator, 16, 16, 8, float> acc[2][4];
    #pragma unroll
    for (int i = 0; i < 2; i++)
        #pragma unroll
        for (int j = 0; j < 4; j++)
            wmma::fill_fragment(acc[i][j], 0.f);

    const int rowA = tid >> 1;          // 0..127
    const int colA = (tid & 1) * 8;     // 0 or 8
    const int rB   = tid >> 4;          // 0..15
    const int cB   = (tid & 15) * 8;    // 0..120

    auto loadTileAsync = [&](int k0, int p) {
        const float* srcA = A + (size_t)(bm + rowA) * K + k0 + colA;
        unsigned int dA = smem_u32(&As[p][rowA][colA]);
        cp16(dA,      srcA);
        cp16(dA + 16, srcA + 4);
        const float* srcB = W + (size_t)(k0 + rB) * N + bn + cB;
        unsigned int dB = smem_u32(&Bs[p][rB][cB]);
        cp16(dB,      srcB);
        cp16(dB + 16, srcB + 4);
    };

    loadTileAsync(0, 0);
    CP_COMMIT();
    CP_WAIT0();
    __syncthreads();

    const int nIter = K / 16;
    for (int it = 0; it < nIter; ++it) {
        const int p = it & 1;
        if (it + 1 < nIter) { loadTileAsync((it + 1) * 16, p ^ 1); CP_COMMIT(); }

        #pragma unroll
        for (int kk = 0; kk < 16; kk += 8) {
            wmma::fragment<wmma::matrix_a, 16, 16, 8, wmma::precision::tf32, wmma::row_major> a0, a1;
            wmma::load_matrix_sync(a0, &As[p][wr*32     ][kk], 24);
            wmma::load_matrix_sync(a1, &As[p][wr*32 + 16][kk], 24);
            frag_to_tf32(a0);
            frag_to_tf32(a1);
            #pragma unroll
            for (int j = 0; j < 4; j++) {
                wmma::fragment<wmma::matrix_b, 16, 16, 8, wmma::precision::tf32, wmma::row_major> b;
                wmma::load_matrix_sync(b, &Bs[p][kk][wc*64 + j*16], 136);
                frag_to_tf32(b);
                wmma::mma_sync(acc[0][j], a0, b, acc[0][j]);
                wmma::mma_sync(acc[1][j], a1, b, acc[1][j]);
            }
        }
        CP_WAIT0();
        __syncthreads();
    }

    // Epilogue: stage each 16x16 tile through smem (alias As[0]), add bias.
    float* stage = &As[0][0][0] + warp * 384;   // 16*24 floats per warp
    const int lr = lane >> 1;          // 0..15
    const int lc = (lane & 1) * 8;     // 0 or 8
    #pragma unroll
    for (int i = 0; i < 2; i++) {
        #pragma unroll
        for (int j = 0; j < 4; j++) {
            wmma::store_matrix_sync(stage, acc[i][j], 24, wmma::mem_row_major);
            __syncwarp();
            const int row  = bm + wr*32 + i*16 + lr;
            const int col0 = bn + wc*64 + j*16 + lc;
            #pragma unroll
            for (int hh = 0; hh < 2; hh++) {
                float4 o;
                o.x = stage[lr*24 + lc + hh*4 + 0] + bias[col0 + hh*4 + 0];
                o.y = stage[lr*24 + lc + hh*4 + 1] + bias[col0 + hh*4 + 1];
                o.z = stage[lr*24 + lc + hh*4 + 2] + bias[col0 + hh*4 + 2];
                o.w = stage[lr*24 + lc + hh*4 + 3] + bias[col0 + hh*4 + 3];
                if (CVT_OUT) {
                    o.x = wmma::__float_to_tf32(o.x);
                    o.y = wmma::__float_to_tf32(o.y);
                    o.z = wmma::__float_to_tf32(o.z);
                    o.w = wmma::__float_to_tf32(o.w);
                }
                *(float4*)(C + (size_t)row * N + col0 + hh*4) = o;
            }
            __syncwarp();
        }
    }
}

// ---------------------------------------------------------------------------
// Flash attention v2 — BYTE-IDENTICAL to the R6-passing version (no cp.async).
// One block = (b,h) x 128-row Q tile. 8 warps; warp w owns q-rows [16w,16w+16).
// ONE __syncthreads per KV tile; K/V double-buffered with scalar prefetch.
// Q persistent in register fragments. No online max. The fp32->tf32
// conversions here are idempotent now (inputs pre-rounded upstream).
// ---------------------------------------------------------------------------
#define LDF 72
#define FLASH_SMEM_FLOATS (4*64*LDF + 128*LDF + 128 + 128)
#define FLASH_SMEM_BYTES  (FLASH_SMEM_FLOATS * 4)

__global__ void __launch_bounds__(256) flash_attn_tf32(
    const float* __restrict__ Q, const float* __restrict__ K,
    const float* __restrict__ V, const float* __restrict__ mask,
    float* __restrict__ ctx)
{
    extern __shared__ float sm[];
    float* Ks    = sm;                    // [2][64][LDF]
    float* Vs    = sm + 2*64*LDF;         // [2][64][LDF]
    float* Ps    = sm + 4*64*LDF;         // [128][LDF] (also Q staging)
    float* l_acc = Ps + 128*LDF;          // [128]
    float* nmask = l_acc + 128;           // [2][64]

    const int tid  = threadIdx.x;
    const int warp = tid >> 5;
    const int lane = tid & 31;
    const int bh   = blockIdx.y;
    const int b    = bh >> 4, h = bh & 15;
    const int q0   = blockIdx.x * 128;

    const float* Qg = Q + ((size_t)(b*SEQ + q0)) * DDIM + h*HDIM;
    const float* Kg = K + ((size_t)(b*SEQ)) * DDIM + h*HDIM;
    const float* Vg = V + ((size_t)(b*SEQ)) * DDIM + h*HDIM;
    const float* mg = mask + b*SEQ;

    // Stage Q [128 x 64] through Ps, converted to tf32 (idempotent now)
    for (int e = tid*4; e < 128*64; e += 1024) {
        const int q = e >> 6, kd = e & 63;
        float4 v4 = *(const float4*)(Qg + (size_t)q * DDIM + kd);
        Ps[q*LDF + kd+0] = wmma::__float_to_tf32(v4.x);
        Ps[q*LDF + kd+1] = wmma::__float_to_tf32(v4.y);
        Ps[q*LDF + kd+2] = wmma::__float_to_tf32(v4.z);
        Ps[q*LDF + kd+3] = wmma::__float_to_tf32(v4.w);
    }
    if (tid < 128) l_acc[tid] = 0.f;
    __syncthreads();

    // Persistent Q fragments: warp w rows [16w, 16w+16), all 64 k-dims
    wmma::fragment<wmma::matrix_a, 16, 16, 8, wmma::precision::tf32, wmma::row_major> q_frag[8];
    #pragma unroll
    for (int kd = 0; kd < 8; kd++)
        wmma::load_matrix_sync(q_frag[kd], &Ps[(warp*16)*LDF + kd*8], LDF);

    wmma::fragment<wmma::accumulator, 16, 16, 8, float> o_acc[4];
    #pragma unroll
    for (int j = 0; j < 4; j++) wmma::fill_fragment(o_acc[j], 0.f);

    // prefetch KV tile t into buffer p (64 rows x 64 cols each)
    const int pr = tid >> 2;           // 0..63
    const int pc = (tid & 3) * 16;     // 0,16,32,48
    auto prefetch = [&](int t, int p) {
        const float* kp = Kg + (size_t)(t*64 + pr) * DDIM + pc;
        const float* vp = Vg + (size_t)(t*64 + pr) * DDIM + pc;
        float* kd = &Ks[p*64*LDF + pr*LDF + pc];
        float* vd = &Vs[p*64*LDF + pr*LDF + pc];
        #pragma unroll
        for (int c = 0; c < 16; c += 4) {
            float4 kv = *(const float4*)(kp + c);
            kd[c+0] = wmma::__float_to_tf32(kv.x);
            kd[c+1] = wmma::__float_to_tf32(kv.y);
            kd[c+2] = wmma::__float_to_tf32(kv.z);
            kd[c+3] = wmma::__float_to_tf32(kv.w);
            float4 vv = *(const float4*)(vp + c);
            vd[c+0] = wmma::__float_to_tf32(vv.x);
            vd[c+1] = wmma::__float_to_tf32(vv.y);
            vd[c+2] = wmma::__float_to_tf32(vv.z);
            vd[c+3] = wmma::__float_to_tf32(vv.w);
        }
        if (tid < 64) nmask[p*64 + tid] = mg[t*64 + tid] * -1e9f;
    };
    prefetch(0, 0);

    const int erow  = warp*16 + (lane >> 1);   // exp row (warp-local!)
    const int epart = lane & 1;                // half-row 0/1
    float* prow = &Ps[erow*LDF + epart*32];

    for (int t = 0; t < SEQ/64; ++t) {
        const int p = t & 1;
        __syncthreads();   // KV[p] ready; prev iter's reads of KV[p^1], Ps done
        if (t + 1 < SEQ/64) prefetch(t + 1, p ^ 1);

        // S = Q @ K^T : warp computes 16 rows x 64 cols (4 n-tiles)
        wmma::fragment<wmma::accumulator, 16, 16, 8, float> s_acc[4];
        #pragma unroll
        for (int j = 0; j < 4; j++) wmma::fill_fragment(s_acc[j], 0.f);
        #pragma unroll
        for (int kd = 0; kd < 8; kd++) {
            #pragma unroll
            for (int j = 0; j < 4; j++) {
                wmma::fragment<wmma::matrix_b, 16, 16, 8, wmma::precision::tf32, wmma::col_major> kb;
                wmma::load_matrix_sync(kb, &Ks[p*64*LDF + (j*16)*LDF + kd*8], LDF);
                wmma::mma_sync(s_acc[j], q_frag[kd], kb, s_acc[j]);
            }
        }
        #pragma unroll
        for (int j = 0; j < 4; j++)
            wmma::store_matrix_sync(&Ps[(warp*16)*LDF + j*16], s_acc[j], LDF, wmma::mem_row_major);
        __syncwarp();

        // exp pass (warp-local rows): P = exp(S*scale + maskterm)
        {
            const float* nm = &nmask[p*64 + epart*32];
            float psum = 0.f;
            #pragma unroll
            for (int c = 0; c < 32; c++) {
                float v = __expf(prow[c] * SCALE + nm[c]);
                prow[c] = wmma::__float_to_tf32(v);
                psum += v;
            }
            psum += __shfl_xor_sync(0xffffffffu, psum, 1);
            if (epart == 0) l_acc[erow] += psum;
        }
        __syncwarp();

        // O += P @ V (warp-local rows of Ps)
        #pragma unroll
        for (int kk = 0; kk < 8; kk++) {
            wmma::fragment<wmma::matrix_a, 16, 16, 8, wmma::precision::tf32, wmma::row_major> pa;
            wmma::load_matrix_sync(pa, &Ps[(warp*16)*LDF + kk*8], LDF);
            #pragma unroll
            for (int j = 0; j < 4; j++) {
                wmma::fragment<wmma::matrix_b, 16, 16, 8, wmma::precision::tf32, wmma::row_major> vb;
                wmma::load_matrix_sync(vb, &Vs[p*64*LDF + (kk*8)*LDF + j*16], LDF);
                wmma::mma_sync(o_acc[j], pa, vb, o_acc[j]);
            }
        }
    }

    // Epilogue: stage O through Ps (warp-local), normalize, write ctx
    #pragma unroll
    for (int j = 0; j < 4; j++)
        wmma::store_matrix_sync(&Ps[(warp*16)*LDF + j*16], o_acc[j], LDF, wmma::mem_row_major);
    __syncwarp();
    {
        const float inv = 1.f / l_acc[erow];
        const int row = b*SEQ + q0 + erow;
        float* dst = ctx + (size_t)row * DDIM + h*HDIM + epart*32;
        #pragma unroll
        for (int c = 0; c < 32; c += 4) {
            float4 o;
            o.x = prow[c+0] * inv;
            o.y = prow[c+1] * inv;
            o.z = prow[c+2] * inv;
            o.w = prow[c+3] * inv;
            *(float4*)(dst + c) = o;
        }
    }
}

// ---------------------------------------------------------------------------
extern "C" void kernel_launch(void* const* d_in, const int* in_sizes, int n_in,
                              void* d_out, int out_size)
{
    const float* query = (const float*)d_in[0];
    const float* key   = (const float*)d_in[1];
    const float* value = (const float*)d_in[2];
    const float* mask  = (const float*)d_in[3];
    const float* Wq    = (const float*)d_in[4];
    const float* bq    = (const float*)d_in[5];
    const float* Wk    = (const float*)d_in[6];
    const float* bk    = (const float*)d_in[7];
    const float* Wv    = (const float*)d_in[8];
    const float* bv    = (const float*)d_in[9];
    const float* Wo    = (const float*)d_in[10];
    const float* bo    = (const float*)d_in[11];
    float* out = (float*)d_out;

    float *Qp, *Kp, *Vp, *Cp;
    cudaGetSymbolAddress((void**)&Qp, g_Q);
    cudaGetSymbolAddress((void**)&Kp, g_K);
    cudaGetSymbolAddress((void**)&Vp, g_V);
    cudaGetSymbolAddress((void**)&Cp, g_ctx);

    cudaFuncSetAttribute(flash_attn_tf32,
                         cudaFuncAttributeMaxDynamicSharedMemorySize,
                         FLASH_SMEM_BYTES);

    dim3 gg(DDIM/128, MROWS/128);   // (8, 64)
    dim3 bb(256);

    // Projections write tf32-rounded values (CVT_OUT=true); flash's own
    // conversions are then idempotent. Final GEMM writes full fp32.
    gemm_tf32_bias<true ><<<gg, bb>>>(query, Wq, bq, Qp, MROWS, DDIM, DDIM);
    gemm_tf32_bias<true ><<<gg, bb>>>(key,   Wk, bk, Kp, MROWS, DDIM, DDIM);
    gemm_tf32_bias<true ><<<gg, bb>>>(value, Wv, bv, Vp, MROWS, DDIM, DDIM);

    dim3 ga(SEQ/128, BATCH*NHEADS); // (16, 64)
    flash_attn_tf32<<<ga, bb, FLASH_SMEM_BYTES>>>(Qp, Kp, Vp, mask, Cp);

    gemm_tf32_bias<false><<<gg, bb>>>(Cp, Wo, bo, out, MROWS, DDIM, DDIM);
}